// round 2
// baseline (speedup 1.0000x reference)
#include <cuda_runtime.h>
#include <cstdint>

// one_hot: label (4096x4096 int32) -> out (8, 4096, 4096) float32
// out[n, h, w] = (label[h, w] == n) ? 1.0f : 0.0f
//
// Pure HBM streaming: 64 MiB read + 512 MiB write (604 MB total, ~75.5us floor
// at 8 TB/s). R1 measured DRAM=70.8% with 1 int4/thread. R2: 2 int4/thread ->
// deeper store queues per warp-slot, 32B/lane fully-coalesced access.

#define H 4096
#define W 4096
#define NCLS 8
#define HW (H * W)          // 16777216
#define NVEC (HW / 4)       // 4194304 float4/int4 vectors per plane
#define VPT 2               // vectors per thread
#define NTHREADS (NVEC / VPT)   // 2097152
#define BLK 256

__global__ void __launch_bounds__(BLK) onehot_kernel(
    const int4* __restrict__ lab4, float4* __restrict__ out4)
{
    unsigned i = (blockIdx.x * (unsigned)BLK + threadIdx.x) * 2u;  // vector index
    int4 a = __ldcs(lab4 + i);
    int4 b = __ldcs(lab4 + i + 1);

#pragma unroll
    for (int n = 0; n < NCLS; n++) {
        float4 va, vb;
        va.x = (a.x == n) ? 1.0f : 0.0f;
        va.y = (a.y == n) ? 1.0f : 0.0f;
        va.z = (a.z == n) ? 1.0f : 0.0f;
        va.w = (a.w == n) ? 1.0f : 0.0f;
        vb.x = (b.x == n) ? 1.0f : 0.0f;
        vb.y = (b.y == n) ? 1.0f : 0.0f;
        vb.z = (b.z == n) ? 1.0f : 0.0f;
        vb.w = (b.w == n) ? 1.0f : 0.0f;
        size_t base = (size_t)n * NVEC + i;
        __stcs(out4 + base, va);
        __stcs(out4 + base + 1, vb);
    }
}

extern "C" void kernel_launch(void* const* d_in, const int* in_sizes, int n_in,
                              void* d_out, int out_size)
{
    const int4* lab4 = (const int4*)d_in[0];
    float4* out4 = (float4*)d_out;
    onehot_kernel<<<NTHREADS / BLK, BLK>>>(lab4, out4);
}

// round 3
// speedup vs baseline: 1.4643x; 1.4643x over previous
#include <cuda_runtime.h>
#include <cstdint>

// one_hot: label (4096x4096 int32) -> out (8, 4096, 4096) float32
// out[n, h, w] = (label[h, w] == n) ? 1.0f : 0.0f
//
// Pure HBM streaming: 64 MiB read + 512 MiB write (~75.5us floor at 8 TB/s).
// R1 (1 vec/thread, coalesced): 94us, DRAM=70.8%.
// R2 (2 adjacent vecs/thread): BROKE per-instruction coalescing (32B lane
//     stride), L1=80.7%, 144us.
// R3: 2 vecs/thread at +BLK offset -> every LDG/STG has contiguous 16B lanes,
//     while keeping 2x in-flight loads + 16 store streams per thread.

#define H 4096
#define W 4096
#define NCLS 8
#define HW (H * W)             // 16777216
#define NVEC (HW / 4)          // 4194304 float4/int4 vectors per plane
#define BLK 256
#define VPT 2
#define VPB (BLK * VPT)        // 512 vectors per block
#define NBLOCKS (NVEC / VPB)   // 8192

__global__ void __launch_bounds__(BLK) onehot_kernel(
    const int4* __restrict__ lab4, float4* __restrict__ out4)
{
    unsigned i = blockIdx.x * (unsigned)VPB + threadIdx.x;  // first vector
    int4 a = __ldcs(lab4 + i);
    int4 b = __ldcs(lab4 + i + BLK);   // second vector, still lane-contiguous

#pragma unroll
    for (int n = 0; n < NCLS; n++) {
        float4 va, vb;
        va.x = (a.x == n) ? 1.0f : 0.0f;
        va.y = (a.y == n) ? 1.0f : 0.0f;
        va.z = (a.z == n) ? 1.0f : 0.0f;
        va.w = (a.w == n) ? 1.0f : 0.0f;
        vb.x = (b.x == n) ? 1.0f : 0.0f;
        vb.y = (b.y == n) ? 1.0f : 0.0f;
        vb.z = (b.z == n) ? 1.0f : 0.0f;
        vb.w = (b.w == n) ? 1.0f : 0.0f;
        size_t base = (size_t)n * NVEC + i;
        __stcs(out4 + base, va);
        __stcs(out4 + base + BLK, vb);
    }
}

extern "C" void kernel_launch(void* const* d_in, const int* in_sizes, int n_in,
                              void* d_out, int out_size)
{
    const int4* lab4 = (const int4*)d_in[0];
    float4* out4 = (float4*)d_out;
    onehot_kernel<<<NBLOCKS, BLK>>>(lab4, out4);
}